// round 3
// baseline (speedup 1.0000x reference)
#include <cuda_runtime.h>
#include <cuda_bf16.h>

#define EPSF 1e-6f
#define TWO_PI_F 6.283185307179586f
#define NB_BASE 32

// Scratch (no device allocation allowed)
__device__ float g_ev[8192];       // per-event A_i * B_i
__device__ float g_base[NB_BASE];  // per-block base-rate partial sums

// ---------------------------------------------------------------------------
// Fused kernel: blocks [0, N) = events, blocks [N, N+NB_BASE) = base-rate.
// ---------------------------------------------------------------------------
__global__ __launch_bounds__(256) void k_fused(
    const float* __restrict__ x, const float* __restrict__ t,
    const float* __restrict__ past_x, const float* __restrict__ past_t,
    const float* __restrict__ cov,
    const float* __restrict__ z, const float* __restrict__ x_grid,
    const float* __restrict__ t_grid, const float* __restrict__ beta,
    const float* __restrict__ p_alpha, const float* __restrict__ p_sigma,
    const float* __restrict__ p_omega,
    int N, int M, int G, int T, int D, int rows,
    float* __restrict__ out)
{
    __shared__ float smS[8], smA[8], smB[8];
    const int tid = threadIdx.x;

    // ================= base-rate partial blocks =================
    if (blockIdx.x >= (unsigned)N) {
        const int bj = blockIdx.x - N;
        float bta[16];
        #pragma unroll
        for (int d = 0; d < 16; d++) bta[d] = (d < D) ? beta[d] : 0.0f;

        float s = 0.0f;
        if (D == 16) {
            for (int r = bj * 256 + tid; r < rows; r += NB_BASE * 256) {
                const float4* __restrict__ zr =
                    reinterpret_cast<const float4*>(z + (size_t)r * 16);
                float4 v0 = zr[0], v1 = zr[1], v2 = zr[2], v3 = zr[3];
                float dot = 0.0f;
                dot = fmaf(v0.x, bta[0],  dot); dot = fmaf(v0.y, bta[1],  dot);
                dot = fmaf(v0.z, bta[2],  dot); dot = fmaf(v0.w, bta[3],  dot);
                dot = fmaf(v1.x, bta[4],  dot); dot = fmaf(v1.y, bta[5],  dot);
                dot = fmaf(v1.z, bta[6],  dot); dot = fmaf(v1.w, bta[7],  dot);
                dot = fmaf(v2.x, bta[8],  dot); dot = fmaf(v2.y, bta[9],  dot);
                dot = fmaf(v2.z, bta[10], dot); dot = fmaf(v2.w, bta[11], dot);
                dot = fmaf(v3.x, bta[12], dot); dot = fmaf(v3.y, bta[13], dot);
                dot = fmaf(v3.z, bta[14], dot); dot = fmaf(v3.w, bta[15], dot);
                s += fmaxf(dot, EPSF);
            }
        } else {
            for (int r = bj * 256 + tid; r < rows; r += NB_BASE * 256) {
                float dot = 0.0f;
                for (int d = 0; d < D; d++)
                    dot = fmaf(z[(size_t)r * D + d], beta[d], dot);
                s += fmaxf(dot, EPSF);
            }
        }
        #pragma unroll
        for (int o = 16; o > 0; o >>= 1)
            s += __shfl_down_sync(0xffffffffu, s, o);
        if ((tid & 31) == 0) smS[tid >> 5] = s;
        __syncthreads();
        if (tid == 0) {
            float S = 0.0f;
            #pragma unroll
            for (int w = 0; w < 8; w++) S += smS[w];
            g_base[bj] = S;
        }
        return;
    }

    // ================= event blocks =================
    const int i = blockIdx.x;

    const float alpha = *p_alpha;
    const float sigma = *p_sigma;
    const float omega = *p_omega;
    const float inv2s2 = 1.0f / (2.0f * sigma * sigma);
    const float Cf     = alpha * omega / (TWO_PI_F * sigma * sigma);

    const float xi = x[2 * i];
    const float yi = x[2 * i + 1];
    const float ti = t[i];

    const float4* __restrict__ pt4 =
        reinterpret_cast<const float4*>(past_t + (size_t)i * M);
    const float4* __restrict__ px4 =
        reinterpret_cast<const float4*>(past_x + (size_t)i * 2 * M);

    float s = 0.0f;

    if (M == 2048) {
        // Front-batched: 6 independent LDG.128 in flight before any compute.
        const int s0 = tid;         // slots of 4 points
        const int s1 = tid + 256;
        float4 tt0 = pt4[s0];
        float4 tt1 = pt4[s1];
        float4 a0  = px4[2 * s0];
        float4 a1  = px4[2 * s0 + 1];
        float4 b0  = px4[2 * s1];
        float4 b1  = px4[2 * s1 + 1];

        {
            float dt, dx, dy, r2, e;
            dt = ti - tt0.x; dx = xi - a0.x; dy = yi - a0.y; r2 = dx*dx + dy*dy;
            e = __expf(-(r2 * inv2s2 + omega * dt)); s += (dt > 0.0f) ? e : 0.0f;
            dt = ti - tt0.y; dx = xi - a0.z; dy = yi - a0.w; r2 = dx*dx + dy*dy;
            e = __expf(-(r2 * inv2s2 + omega * dt)); s += (dt > 0.0f) ? e : 0.0f;
            dt = ti - tt0.z; dx = xi - a1.x; dy = yi - a1.y; r2 = dx*dx + dy*dy;
            e = __expf(-(r2 * inv2s2 + omega * dt)); s += (dt > 0.0f) ? e : 0.0f;
            dt = ti - tt0.w; dx = xi - a1.z; dy = yi - a1.w; r2 = dx*dx + dy*dy;
            e = __expf(-(r2 * inv2s2 + omega * dt)); s += (dt > 0.0f) ? e : 0.0f;
            dt = ti - tt1.x; dx = xi - b0.x; dy = yi - b0.y; r2 = dx*dx + dy*dy;
            e = __expf(-(r2 * inv2s2 + omega * dt)); s += (dt > 0.0f) ? e : 0.0f;
            dt = ti - tt1.y; dx = xi - b0.z; dy = yi - b0.w; r2 = dx*dx + dy*dy;
            e = __expf(-(r2 * inv2s2 + omega * dt)); s += (dt > 0.0f) ? e : 0.0f;
            dt = ti - tt1.z; dx = xi - b1.x; dy = yi - b1.y; r2 = dx*dx + dy*dy;
            e = __expf(-(r2 * inv2s2 + omega * dt)); s += (dt > 0.0f) ? e : 0.0f;
            dt = ti - tt1.w; dx = xi - b1.z; dy = yi - b1.w; r2 = dx*dx + dy*dy;
            e = __expf(-(r2 * inv2s2 + omega * dt)); s += (dt > 0.0f) ? e : 0.0f;
        }
    } else {
        // generic fallback: 4 points per slot
        for (int sl = tid; sl < M / 4; sl += 256) {
            float4 tt = pt4[sl];
            float4 p0 = px4[2 * sl];
            float4 p1 = px4[2 * sl + 1];
            float dt, dx, dy, r2, e;
            dt = ti - tt.x; dx = xi - p0.x; dy = yi - p0.y; r2 = dx*dx + dy*dy;
            e = __expf(-(r2 * inv2s2 + omega * dt)); s += (dt > 0.0f) ? e : 0.0f;
            dt = ti - tt.y; dx = xi - p0.z; dy = yi - p0.w; r2 = dx*dx + dy*dy;
            e = __expf(-(r2 * inv2s2 + omega * dt)); s += (dt > 0.0f) ? e : 0.0f;
            dt = ti - tt.z; dx = xi - p1.x; dy = yi - p1.y; r2 = dx*dx + dy*dy;
            e = __expf(-(r2 * inv2s2 + omega * dt)); s += (dt > 0.0f) ? e : 0.0f;
            dt = ti - tt.w; dx = xi - p1.z; dy = yi - p1.w; r2 = dx*dx + dy*dy;
            e = __expf(-(r2 * inv2s2 + omega * dt)); s += (dt > 0.0f) ? e : 0.0f;
        }
    }

    // ---- spatial grid factor A_i ----
    float a = 0.0f;
    const float2* __restrict__ gx = reinterpret_cast<const float2*>(x_grid);
    for (int g = tid; g < G; g += 256) {
        float2 p  = gx[g];
        float  dx = p.x - xi;
        float  dy = p.y - yi;
        a += __expf(-(dx * dx + dy * dy) * inv2s2);
    }

    // ---- temporal grid factor B_i ----
    float b = 0.0f;
    for (int k = tid; k < T; k += 256) {
        float dtau = t_grid[k] - ti;
        if (dtau > 0.0f)
            b += __expf(-omega * dtau);
    }

    // ---- deterministic block reductions ----
    #pragma unroll
    for (int o = 16; o > 0; o >>= 1) {
        s += __shfl_down_sync(0xffffffffu, s, o);
        a += __shfl_down_sync(0xffffffffu, a, o);
        b += __shfl_down_sync(0xffffffffu, b, o);
    }
    const int warp = tid >> 5;
    const int lane = tid & 31;
    if (lane == 0) { smS[warp] = s; smA[warp] = a; smB[warp] = b; }
    __syncthreads();

    if (tid == 0) {
        float S = 0.0f, A = 0.0f, B = 0.0f;
        #pragma unroll
        for (int w = 0; w < 8; w++) { S += smS[w]; A += smA[w]; B += smB[w]; }

        float mu = 0.0f;
        const float* __restrict__ ci = cov + (size_t)i * D;
        for (int d = 0; d < D; d++) mu = fmaf(ci[d], beta[d], mu);
        mu = fmaxf(mu, EPSF);

        float lam = mu + Cf * S;
        out[i]    = logf(lam + EPSF);
        g_ev[i]   = A * B;
    }
}

// ---------------------------------------------------------------------------
// Final deterministic reduce -> out[N] = integral
// ---------------------------------------------------------------------------
__global__ __launch_bounds__(256) void k_final(
    const float* __restrict__ t_grid,
    const float* __restrict__ p_alpha, const float* __restrict__ p_sigma,
    const float* __restrict__ p_omega,
    int N, int G,
    float* __restrict__ out)
{
    __shared__ float smE[8], smB[8];
    const int tid = threadIdx.x;

    float e = 0.0f;
    for (int i = tid; i < N; i += 256) e += g_ev[i];
    float b = (tid < NB_BASE) ? g_base[tid] : 0.0f;

    #pragma unroll
    for (int o = 16; o > 0; o >>= 1) {
        e += __shfl_down_sync(0xffffffffu, e, o);
        b += __shfl_down_sync(0xffffffffu, b, o);
    }
    if ((tid & 31) == 0) { smE[tid >> 5] = e; smB[tid >> 5] = b; }
    __syncthreads();

    if (tid == 0) {
        float E = 0.0f, B = 0.0f;
        #pragma unroll
        for (int w = 0; w < 8; w++) { E += smE[w]; B += smB[w]; }

        const float alpha = *p_alpha;
        const float sigma = *p_sigma;
        const float omega = *p_omega;
        const float Cf = alpha * omega / (TWO_PI_F * sigma * sigma);
        const float dt_step = t_grid[1] - t_grid[0];
        const float dxdy = 1.0f / (float)G;

        out[N] = (B + Cf * E) * dxdy * dt_step;
    }
}

// ---------------------------------------------------------------------------
extern "C" void kernel_launch(void* const* d_in, const int* in_sizes, int n_in,
                              void* d_out, int out_size)
{
    const float* x       = (const float*)d_in[0];
    const float* t       = (const float*)d_in[1];
    const float* past_x  = (const float*)d_in[2];
    const float* past_t  = (const float*)d_in[3];
    const float* cov     = (const float*)d_in[4];
    const float* z_grid  = (const float*)d_in[5];
    const float* x_grid  = (const float*)d_in[6];
    const float* t_grid  = (const float*)d_in[7];
    const float* beta    = (const float*)d_in[8];
    const float* p_alpha = (const float*)d_in[9];
    const float* p_sigma = (const float*)d_in[10];
    const float* p_omega = (const float*)d_in[11];
    float* out = (float*)d_out;

    const int N = in_sizes[1];
    const int M = in_sizes[3] / N;
    const int D = in_sizes[8];
    const int G = in_sizes[6] / 2;
    const int T = in_sizes[7];
    const int rows = in_sizes[5] / D;   // T*G

    k_fused<<<N + NB_BASE, 256>>>(x, t, past_x, past_t, cov, z_grid, x_grid,
                                  t_grid, beta, p_alpha, p_sigma, p_omega,
                                  N, M, G, T, D, rows, out);
    k_final<<<1, 256>>>(t_grid, p_alpha, p_sigma, p_omega, N, G, out);
}

// round 6
// speedup vs baseline: 1.1278x; 1.1278x over previous
#include <cuda_runtime.h>
#include <cuda_bf16.h>

#define EPSF 1e-6f
#define TWO_PI_F 6.283185307179586f
#define NB_BASE 32

// Scratch (no device allocation allowed)
__device__ float g_ev[8192];       // per-event A_i * B_i
__device__ float g_base[NB_BASE];  // per-block base-rate partial sums
__device__ int   g_count = 0;      // arrival counter (reset by last block)

// ---------------------------------------------------------------------------
// Single fused kernel.
//   blocks [0, NB_BASE)            : base-rate grid partial sums
//   blocks [NB_BASE, NB_BASE + N)  : per-event excitation + grid factors
// The LAST block to finish performs the final deterministic reduction and
// writes out[N] (the integral). Counter protocol is bit-deterministic.
// ---------------------------------------------------------------------------
__global__ __launch_bounds__(256) void k_fused(
    const float* __restrict__ x, const float* __restrict__ t,
    const float* __restrict__ past_x, const float* __restrict__ past_t,
    const float* __restrict__ cov,
    const float* __restrict__ z, const float* __restrict__ x_grid,
    const float* __restrict__ t_grid, const float* __restrict__ beta,
    const float* __restrict__ p_alpha, const float* __restrict__ p_sigma,
    const float* __restrict__ p_omega,
    int N, int M, int G, int T, int D, int rows,
    float* __restrict__ out)
{
    __shared__ float smS[8], smA[8], smB[8];
    __shared__ int   sm_last;
    const int tid = threadIdx.x;

    const float alpha = *p_alpha;
    const float sigma = *p_sigma;
    const float omega = *p_omega;
    const float inv2s2 = 1.0f / (2.0f * sigma * sigma);
    const float Cf     = alpha * omega / (TWO_PI_F * sigma * sigma);

    if (blockIdx.x < (unsigned)NB_BASE) {
        // ================= base-rate partial blocks =================
        const int bj = blockIdx.x;
        float bta[16];
        #pragma unroll
        for (int d = 0; d < 16; d++) bta[d] = (d < D) ? beta[d] : 0.0f;

        float s = 0.0f;
        if (D == 16) {
            for (int r = bj * 256 + tid; r < rows; r += NB_BASE * 256) {
                const float4* __restrict__ zr =
                    reinterpret_cast<const float4*>(z + (size_t)r * 16);
                float4 v0 = zr[0], v1 = zr[1], v2 = zr[2], v3 = zr[3];
                float dot = 0.0f;
                dot = fmaf(v0.x, bta[0],  dot); dot = fmaf(v0.y, bta[1],  dot);
                dot = fmaf(v0.z, bta[2],  dot); dot = fmaf(v0.w, bta[3],  dot);
                dot = fmaf(v1.x, bta[4],  dot); dot = fmaf(v1.y, bta[5],  dot);
                dot = fmaf(v1.z, bta[6],  dot); dot = fmaf(v1.w, bta[7],  dot);
                dot = fmaf(v2.x, bta[8],  dot); dot = fmaf(v2.y, bta[9],  dot);
                dot = fmaf(v2.z, bta[10], dot); dot = fmaf(v2.w, bta[11], dot);
                dot = fmaf(v3.x, bta[12], dot); dot = fmaf(v3.y, bta[13], dot);
                dot = fmaf(v3.z, bta[14], dot); dot = fmaf(v3.w, bta[15], dot);
                s += fmaxf(dot, EPSF);
            }
        } else {
            for (int r = bj * 256 + tid; r < rows; r += NB_BASE * 256) {
                float dot = 0.0f;
                for (int d = 0; d < D; d++)
                    dot = fmaf(z[(size_t)r * D + d], beta[d], dot);
                s += fmaxf(dot, EPSF);
            }
        }
        #pragma unroll
        for (int o = 16; o > 0; o >>= 1)
            s += __shfl_down_sync(0xffffffffu, s, o);
        if ((tid & 31) == 0) smS[tid >> 5] = s;
        __syncthreads();
        if (tid == 0) {
            float S = 0.0f;
            #pragma unroll
            for (int w = 0; w < 8; w++) S += smS[w];
            g_base[bj] = S;
        }
    } else {
        // ================= event blocks =================
        const int i = blockIdx.x - NB_BASE;

        const float xi = x[2 * i];
        const float yi = x[2 * i + 1];
        const float ti = t[i];

        const float4* __restrict__ pt4 =
            reinterpret_cast<const float4*>(past_t + (size_t)i * M);
        const float4* __restrict__ px4 =
            reinterpret_cast<const float4*>(past_x + (size_t)i * 2 * M);

        float s = 0.0f;

        if (M == 2048) {
            // Front-batched: 6 independent LDG.128 in flight before compute.
            const int s0 = tid;
            const int s1 = tid + 256;
            float4 tt0 = pt4[s0];
            float4 tt1 = pt4[s1];
            float4 a0  = px4[2 * s0];
            float4 a1  = px4[2 * s0 + 1];
            float4 b0  = px4[2 * s1];
            float4 b1  = px4[2 * s1 + 1];

            float dt, dx, dy, r2, e;
            dt = ti - tt0.x; dx = xi - a0.x; dy = yi - a0.y; r2 = dx*dx + dy*dy;
            e = __expf(-(r2 * inv2s2 + omega * dt)); s += (dt > 0.0f) ? e : 0.0f;
            dt = ti - tt0.y; dx = xi - a0.z; dy = yi - a0.w; r2 = dx*dx + dy*dy;
            e = __expf(-(r2 * inv2s2 + omega * dt)); s += (dt > 0.0f) ? e : 0.0f;
            dt = ti - tt0.z; dx = xi - a1.x; dy = yi - a1.y; r2 = dx*dx + dy*dy;
            e = __expf(-(r2 * inv2s2 + omega * dt)); s += (dt > 0.0f) ? e : 0.0f;
            dt = ti - tt0.w; dx = xi - a1.z; dy = yi - a1.w; r2 = dx*dx + dy*dy;
            e = __expf(-(r2 * inv2s2 + omega * dt)); s += (dt > 0.0f) ? e : 0.0f;
            dt = ti - tt1.x; dx = xi - b0.x; dy = yi - b0.y; r2 = dx*dx + dy*dy;
            e = __expf(-(r2 * inv2s2 + omega * dt)); s += (dt > 0.0f) ? e : 0.0f;
            dt = ti - tt1.y; dx = xi - b0.z; dy = yi - b0.w; r2 = dx*dx + dy*dy;
            e = __expf(-(r2 * inv2s2 + omega * dt)); s += (dt > 0.0f) ? e : 0.0f;
            dt = ti - tt1.z; dx = xi - b1.x; dy = yi - b1.y; r2 = dx*dx + dy*dy;
            e = __expf(-(r2 * inv2s2 + omega * dt)); s += (dt > 0.0f) ? e : 0.0f;
            dt = ti - tt1.w; dx = xi - b1.z; dy = yi - b1.w; r2 = dx*dx + dy*dy;
            e = __expf(-(r2 * inv2s2 + omega * dt)); s += (dt > 0.0f) ? e : 0.0f;
        } else {
            for (int sl = tid; sl < M / 4; sl += 256) {
                float4 tt = pt4[sl];
                float4 p0 = px4[2 * sl];
                float4 p1 = px4[2 * sl + 1];
                float dt, dx, dy, r2, e;
                dt = ti - tt.x; dx = xi - p0.x; dy = yi - p0.y; r2 = dx*dx + dy*dy;
                e = __expf(-(r2 * inv2s2 + omega * dt)); s += (dt > 0.0f) ? e : 0.0f;
                dt = ti - tt.y; dx = xi - p0.z; dy = yi - p0.w; r2 = dx*dx + dy*dy;
                e = __expf(-(r2 * inv2s2 + omega * dt)); s += (dt > 0.0f) ? e : 0.0f;
                dt = ti - tt.z; dx = xi - p1.x; dy = yi - p1.y; r2 = dx*dx + dy*dy;
                e = __expf(-(r2 * inv2s2 + omega * dt)); s += (dt > 0.0f) ? e : 0.0f;
                dt = ti - tt.w; dx = xi - p1.z; dy = yi - p1.w; r2 = dx*dx + dy*dy;
                e = __expf(-(r2 * inv2s2 + omega * dt)); s += (dt > 0.0f) ? e : 0.0f;
            }
        }

        // ---- spatial grid factor A_i ----
        float a = 0.0f;
        const float2* __restrict__ gx = reinterpret_cast<const float2*>(x_grid);
        for (int g = tid; g < G; g += 256) {
            float2 p  = gx[g];
            float  dx = p.x - xi;
            float  dy = p.y - yi;
            a += __expf(-(dx * dx + dy * dy) * inv2s2);
        }

        // ---- temporal grid factor B_i ----
        float b = 0.0f;
        for (int k = tid; k < T; k += 256) {
            float dtau = t_grid[k] - ti;
            if (dtau > 0.0f)
                b += __expf(-omega * dtau);
        }

        // ---- deterministic block reductions ----
        #pragma unroll
        for (int o = 16; o > 0; o >>= 1) {
            s += __shfl_down_sync(0xffffffffu, s, o);
            a += __shfl_down_sync(0xffffffffu, a, o);
            b += __shfl_down_sync(0xffffffffu, b, o);
        }
        const int warp = tid >> 5;
        const int lane = tid & 31;
        if (lane == 0) { smS[warp] = s; smA[warp] = a; smB[warp] = b; }
        __syncthreads();

        if (tid == 0) {
            float S = 0.0f, A = 0.0f, B = 0.0f;
            #pragma unroll
            for (int w = 0; w < 8; w++) { S += smS[w]; A += smA[w]; B += smB[w]; }

            float mu = 0.0f;
            const float* __restrict__ ci = cov + (size_t)i * D;
            for (int d = 0; d < D; d++) mu = fmaf(ci[d], beta[d], mu);
            mu = fmaxf(mu, EPSF);

            float lam = mu + Cf * S;
            out[i]    = logf(lam + EPSF);
            g_ev[i]   = A * B;
        }
    }

    // ================= last-block final reduction =================
    __syncthreads();
    if (tid == 0) {
        __threadfence();
        int prev = atomicAdd(&g_count, 1);
        sm_last = (prev == (int)gridDim.x - 1) ? 1 : 0;
    }
    __syncthreads();

    if (sm_last) {
        __threadfence();   // make all partials visible to this block

        float e = 0.0f;
        for (int i2 = tid; i2 < N; i2 += 256) e += g_ev[i2];
        float b2 = (tid < NB_BASE) ? g_base[tid] : 0.0f;

        #pragma unroll
        for (int o = 16; o > 0; o >>= 1) {
            e  += __shfl_down_sync(0xffffffffu, e, o);
            b2 += __shfl_down_sync(0xffffffffu, b2, o);
        }
        if ((tid & 31) == 0) { smS[tid >> 5] = e; smA[tid >> 5] = b2; }
        __syncthreads();

        if (tid == 0) {
            float E = 0.0f, B2 = 0.0f;
            #pragma unroll
            for (int w = 0; w < 8; w++) { E += smS[w]; B2 += smA[w]; }

            const float dt_step = t_grid[1] - t_grid[0];
            const float dxdy = 1.0f / (float)G;
            out[N] = (B2 + Cf * E) * dxdy * dt_step;

            g_count = 0;   // reset for next graph replay
        }
    }
}

// ---------------------------------------------------------------------------
extern "C" void kernel_launch(void* const* d_in, const int* in_sizes, int n_in,
                              void* d_out, int out_size)
{
    const float* x       = (const float*)d_in[0];
    const float* t       = (const float*)d_in[1];
    const float* past_x  = (const float*)d_in[2];
    const float* past_t  = (const float*)d_in[3];
    const float* cov     = (const float*)d_in[4];
    const float* z_grid  = (const float*)d_in[5];
    const float* x_grid  = (const float*)d_in[6];
    const float* t_grid  = (const float*)d_in[7];
    const float* beta    = (const float*)d_in[8];
    const float* p_alpha = (const float*)d_in[9];
    const float* p_sigma = (const float*)d_in[10];
    const float* p_omega = (const float*)d_in[11];
    float* out = (float*)d_out;

    const int N = in_sizes[1];
    const int M = in_sizes[3] / N;
    const int D = in_sizes[8];
    const int G = in_sizes[6] / 2;
    const int T = in_sizes[7];
    const int rows = in_sizes[5] / D;   // T*G

    k_fused<<<N + NB_BASE, 256>>>(x, t, past_x, past_t, cov, z_grid, x_grid,
                                  t_grid, beta, p_alpha, p_sigma, p_omega,
                                  N, M, G, T, D, rows, out);
}